// round 3
// baseline (speedup 1.0000x reference)
#include <cuda_runtime.h>
#include <math.h>

#define S 512
#define B 64
#define D 1024
#define H 1024
#define H2 512
#define G3 1536
#define GIN 2080
#define LN_EPS 1e-5f
#define NBLK 128

// ---------------- scratch (device globals; no allocation) ----------------
__device__ float g_XPF[S * B * G3];        // forward  x-proj
__device__ float g_XPB[S * B * G3];        // backward x-proj
__device__ float g_MEM[S * B * H];         // GRU outputs [s][b][h]
__device__ float g_HST[2][2][B * H2];      // [dir][parity] hidden double-buffer
__device__ float g_PREV[B * H];            // recurrent prop state
__device__ float g_GATED[B * H];           // gate output per step
__device__ float g_H1[B * H];              // emo hidden (pre-LN)
__device__ float g_PS[NBLK * B];           // per-block partial row sums
__device__ float g_PS2[NBLK * B];          // per-block partial row sumsq

// ---------------- software grid barrier ----------------
__device__ volatile unsigned g_flag = 0;
__device__ unsigned g_count = 0;

__device__ __forceinline__ void grid_sync() {
    __syncthreads();
    if (threadIdx.x == 0) {
        unsigned old = g_flag;
        __threadfence();
        if (atomicAdd(&g_count, 1) == (unsigned)(gridDim.x - 1)) {
            g_count = 0;
            __threadfence();
            g_flag = old + 1;
        } else {
            while (g_flag == old) { __nanosleep(64); }
        }
        __threadfence();
    }
    __syncthreads();
}

__device__ __forceinline__ float sigf(float x) { return 1.0f / (1.0f + expf(-x)); }

// ---------------- xproj: [S*B,1024] @ [1024,3072] (Wih_f ++ Wih_b) ----------------
__global__ void k_xproj(const float* __restrict__ utt,
                        const float* __restrict__ Wih_f, const float* __restrict__ bih_f,
                        const float* __restrict__ Wih_b, const float* __restrict__ bih_b) {
    __shared__ float As[16][65];
    __shared__ float Bs[16][65];
    const int s  = blockIdx.x;
    const int n0 = blockIdx.y * 64;
    const bool isF = (n0 < G3);
    const float* __restrict__ W    = isF ? Wih_f : Wih_b;
    const float* __restrict__ bias = isF ? bih_f : bih_b;
    float* __restrict__ Out        = isF ? g_XPF : g_XPB;
    const int nw0 = isF ? n0 : (n0 - G3);

    const int tid = threadIdx.x;
    const int tx = tid & 15, ty = tid >> 4;
    const int lr = tid >> 2, lk = (tid & 3) * 4;

    float acc[4][4];
#pragma unroll
    for (int i = 0; i < 4; i++)
#pragma unroll
        for (int j = 0; j < 4; j++) acc[i][j] = 0.f;

    const float* arow = utt + (size_t)lr * (S * D) + (size_t)s * D;
    const float* brow = W + (size_t)(nw0 + lr) * D;

    for (int k0 = 0; k0 < D; k0 += 16) {
        float4 av = *(const float4*)(arow + k0 + lk);
        As[lk + 0][lr] = av.x; As[lk + 1][lr] = av.y; As[lk + 2][lr] = av.z; As[lk + 3][lr] = av.w;
        float4 bv = *(const float4*)(brow + k0 + lk);
        Bs[lk + 0][lr] = bv.x; Bs[lk + 1][lr] = bv.y; Bs[lk + 2][lr] = bv.z; Bs[lk + 3][lr] = bv.w;
        __syncthreads();
#pragma unroll
        for (int kk = 0; kk < 16; kk++) {
            float a[4], b[4];
#pragma unroll
            for (int u = 0; u < 4; u++) a[u] = As[kk][ty * 4 + u];
#pragma unroll
            for (int u = 0; u < 4; u++) b[u] = Bs[kk][tx * 4 + u];
#pragma unroll
            for (int i = 0; i < 4; i++)
#pragma unroll
                for (int j = 0; j < 4; j++) acc[i][j] += a[i] * b[j];
        }
        __syncthreads();
    }
#pragma unroll
    for (int i = 0; i < 4; i++) {
        int b_ = ty * 4 + i;
#pragma unroll
        for (int j = 0; j < 4; j++) {
            int n = nw0 + tx * 4 + j;
            Out[((size_t)s * B + b_) * G3 + n] = acc[i][j] + bias[n];
        }
    }
}

// ---------------- GRU: all 512 steps in one persistent kernel ----------------
__global__ void k_gru_all(const float* __restrict__ Whh_f, const float* __restrict__ Whh_b,
                          const float* __restrict__ bhh_f, const float* __restrict__ bhh_b) {
    __shared__ float Hs[16][65];
    __shared__ float Ws[16][25];
    const int bx  = blockIdx.x;
    const int dir = bx >> 6;
    const int j0  = (bx & 63) * 8;
    const float* __restrict__ Whh = dir ? Whh_b : Whh_f;
    const float* __restrict__ bhh = dir ? bhh_b : bhh_f;
    const int tid = threadIdx.x;
    const int tb = tid & 31, tj = tid >> 5;
    const int lr = tid >> 2, lk = (tid & 3) * 4;

    // zero hidden state double-buffers (re-done each launch/replay)
    for (int i = bx * 256 + tid; i < 2 * 2 * B * H2; i += NBLK * 256)
        (&g_HST[0][0][0])[i] = 0.0f;
    grid_sync();

    const int c  = tid >> 2;           // Ws loader (valid when tid < 96)
    const int jj = c / 3, gg = c % 3;
    const float* wrow = Whh + (size_t)(gg * H2 + j0 + jj) * H2;
    const int j = j0 + tj;
    const float bR = bhh[j], bZ = bhh[512 + j], bN = bhh[1024 + j];

    for (int t = 0; t < S; t++) {
        const float* __restrict__ hold = g_HST[dir][t & 1];
        float* __restrict__ hnew       = g_HST[dir][(t + 1) & 1];
        const float* __restrict__ XP = dir ? (g_XPB + (size_t)(S - 1 - t) * B * G3)
                                           : (g_XPF + (size_t)t * B * G3);
        float aR[2] = {0.f, 0.f}, aZ[2] = {0.f, 0.f}, aN[2] = {0.f, 0.f};

        for (int k0 = 0; k0 < H2; k0 += 16) {
            float4 hv = *(const float4*)(hold + lr * H2 + k0 + lk);
            Hs[lk + 0][lr] = hv.x; Hs[lk + 1][lr] = hv.y; Hs[lk + 2][lr] = hv.z; Hs[lk + 3][lr] = hv.w;
            if (tid < 96) {
                float4 wv = *(const float4*)(wrow + k0 + lk);
                Ws[lk + 0][c] = wv.x; Ws[lk + 1][c] = wv.y; Ws[lk + 2][c] = wv.z; Ws[lk + 3][c] = wv.w;
            }
            __syncthreads();
#pragma unroll
            for (int kk = 0; kk < 16; kk++) {
                float h0 = Hs[kk][tb], h1 = Hs[kk][tb + 32];
                float wr = Ws[kk][tj * 3 + 0], wz = Ws[kk][tj * 3 + 1], wn = Ws[kk][tj * 3 + 2];
                aR[0] += h0 * wr; aZ[0] += h0 * wz; aN[0] += h0 * wn;
                aR[1] += h1 * wr; aZ[1] += h1 * wz; aN[1] += h1 * wn;
            }
            __syncthreads();
        }
        const int s_out = dir ? (S - 1 - t) : t;
#pragma unroll
        for (int u = 0; u < 2; u++) {
            int b_ = tb + u * 32;
            const float* xrow = XP + (size_t)b_ * G3;
            float xr = xrow[j], xz = xrow[512 + j], xn = xrow[1024 + j];
            float r  = sigf(xr + aR[u] + bR);
            float z  = sigf(xz + aZ[u] + bZ);
            float nn = tanhf(xn + r * (aN[u] + bN));
            float hp = hold[b_ * H2 + j];
            float h  = (1.f - z) * nn + z * hp;
            hnew[b_ * H2 + j] = h;
            g_MEM[((size_t)s_out * B + b_) * H + dir * H2 + j] = h;
        }
        grid_sync();
    }
}

// ---------------- gating loop phases ----------------
__device__ void gate_phase(int t,
                           const float* __restrict__ Wf, const float* __restrict__ Wi,
                           const float* __restrict__ Wo, const float* __restrict__ Wc,
                           const float* __restrict__ bf, const float* __restrict__ bi,
                           const float* __restrict__ bo, const float* __restrict__ bc,
                           const float* __restrict__ spk, const float* __restrict__ pos,
                           float Cs[16][65], float Ws[16][33]) {
    const int j0  = blockIdx.x * 8;
    const int tid = threadIdx.x;
    const int tb = tid & 31, tj = tid >> 5;
    const int lr = tid >> 2, lk = (tid & 3) * 4;
    float acc[2][4];
#pragma unroll
    for (int u = 0; u < 2; u++)
#pragma unroll
        for (int g = 0; g < 4; g++) acc[u][g] = 0.f;

    const float* __restrict__ memrow = g_MEM + (size_t)t * B * H;

    const int c  = tid >> 2;           // Ws loader (valid when tid < 128)
    const int jj = c >> 2, gg = c & 3;
    const float* wsel = (gg == 0) ? Wf : ((gg == 1) ? Wi : ((gg == 2) ? Wo : Wc));
    const float* wrow = wsel + (size_t)(j0 + jj) * GIN;

    for (int k0 = 0; k0 < GIN; k0 += 16) {
        const int k = k0 + lk;
        float4 v;
        if (k < 1024)      v = *(const float4*)(memrow + (size_t)lr * H + k);
        else if (k < 2048) v = *(const float4*)(g_PREV + (size_t)lr * H + (k - 1024));
        else if (k < 2064) v = *(const float4*)(spk + ((size_t)lr * S + t) * 16 + (k - 2048));
        else               v = *(const float4*)(pos + ((size_t)lr * S + t) * 16 + (k - 2064));
        Cs[lk + 0][lr] = v.x; Cs[lk + 1][lr] = v.y; Cs[lk + 2][lr] = v.z; Cs[lk + 3][lr] = v.w;
        if (tid < 128) {
            float4 wv = *(const float4*)(wrow + k0 + lk);
            Ws[lk + 0][c] = wv.x; Ws[lk + 1][c] = wv.y; Ws[lk + 2][c] = wv.z; Ws[lk + 3][c] = wv.w;
        }
        __syncthreads();
#pragma unroll
        for (int kk = 0; kk < 16; kk++) {
            float a0 = Cs[kk][tb], a1 = Cs[kk][tb + 32];
#pragma unroll
            for (int g = 0; g < 4; g++) {
                float w = Ws[kk][tj * 4 + g];
                acc[0][g] += a0 * w;
                acc[1][g] += a1 * w;
            }
        }
        __syncthreads();
    }
    const int j = j0 + tj;
    const float bfv = bf[j], biv = bi[j], bov = bo[j], bcv = bc[j];
#pragma unroll
    for (int u = 0; u < 2; u++) {
        int b_ = tb + u * 32;
        float f  = sigf(acc[u][0] + bfv);
        float ig = sigf(acc[u][1] + biv);
        float o  = sigf(acc[u][2] + bov);
        float cg = tanhf(acc[u][3] + bcv);
        float pv = g_PREV[b_ * H + j];
        float ns = f * pv + ig * cg;
        g_GATED[b_ * H + j] = o * tanhf(ns);
    }
}

__device__ void emo1_phase(const float* __restrict__ x,
                           const float* __restrict__ W1e, const float* __restrict__ b1e,
                           float Xs[16][65], float Ws[16][9],
                           float psum[8][64], float psq[8][64]) {
    const int j0  = blockIdx.x * 8;
    const int tid = threadIdx.x;
    const int tb = tid & 31, tj = tid >> 5;
    const int lr = tid >> 2, lk = (tid & 3) * 4;
    float acc[2] = {0.f, 0.f};
    const int c = tid >> 2;            // Ws loader (valid tid < 32)
    const float* wrow = W1e + (size_t)(j0 + c) * H;

    for (int k0 = 0; k0 < H; k0 += 16) {
        float4 xv = *(const float4*)(x + (size_t)lr * H + k0 + lk);
        Xs[lk + 0][lr] = xv.x; Xs[lk + 1][lr] = xv.y; Xs[lk + 2][lr] = xv.z; Xs[lk + 3][lr] = xv.w;
        if (tid < 32) {
            float4 wv = *(const float4*)(wrow + k0 + lk);
            Ws[lk + 0][c] = wv.x; Ws[lk + 1][c] = wv.y; Ws[lk + 2][c] = wv.z; Ws[lk + 3][c] = wv.w;
        }
        __syncthreads();
#pragma unroll
        for (int kk = 0; kk < 16; kk++) {
            float w = Ws[kk][tj];
            acc[0] += Xs[kk][tb] * w;
            acc[1] += Xs[kk][tb + 32] * w;
        }
        __syncthreads();
    }
    const int j = j0 + tj;
    float v0 = acc[0] + b1e[j];
    float v1 = acc[1] + b1e[j];
    g_H1[(size_t)tb * H + j] = v0;
    g_H1[(size_t)(tb + 32) * H + j] = v1;
    psum[tj][tb] = v0;       psum[tj][tb + 32] = v1;
    psq[tj][tb]  = v0 * v0;  psq[tj][tb + 32]  = v1 * v1;
    __syncthreads();
    if (tid < 64) {
        float s = 0.f, s2 = 0.f;
#pragma unroll
        for (int q = 0; q < 8; q++) { s += psum[q][tid]; s2 += psq[q][tid]; }
        g_PS[blockIdx.x * B + tid]  = s;
        g_PS2[blockIdx.x * B + tid] = s2;
    }
}

__device__ void emo2_phase(int t, const float* __restrict__ res,
                           const float* __restrict__ W2e, const float* __restrict__ b2e,
                           float* __restrict__ out,
                           float Xs[16][65], float Ws[16][9],
                           float mu_s[64], float rs_s[64],
                           const float* gl_s, const float* bl_s) {
    const int j0  = blockIdx.x * 8;
    const int tid = threadIdx.x;
    const int tb = tid & 31, tj = tid >> 5;
    const int lr = tid >> 2, lk = (tid & 3) * 4;

    if (tid < 64) {
        float s = 0.f, s2 = 0.f;
        for (int q = 0; q < NBLK; q++) { s += g_PS[q * B + tid]; s2 += g_PS2[q * B + tid]; }
        float mu  = s * (1.0f / H);
        float var = s2 * (1.0f / H) - mu * mu;
        mu_s[tid] = mu;
        rs_s[tid] = rsqrtf(var + LN_EPS);
    }
    __syncthreads();

    float acc[2] = {0.f, 0.f};
    const int c = tid >> 2;
    const float* wrow = W2e + (size_t)(j0 + c) * H;
    const float mu_l = mu_s[lr], rs_l = rs_s[lr];

    for (int k0 = 0; k0 < H; k0 += 16) {
        float4 xv = *(const float4*)(g_H1 + (size_t)lr * H + k0 + lk);
        float t0 = fmaxf((xv.x - mu_l) * rs_l * gl_s[k0 + lk + 0] + bl_s[k0 + lk + 0], 0.f);
        float t1 = fmaxf((xv.y - mu_l) * rs_l * gl_s[k0 + lk + 1] + bl_s[k0 + lk + 1], 0.f);
        float t2 = fmaxf((xv.z - mu_l) * rs_l * gl_s[k0 + lk + 2] + bl_s[k0 + lk + 2], 0.f);
        float t3 = fmaxf((xv.w - mu_l) * rs_l * gl_s[k0 + lk + 3] + bl_s[k0 + lk + 3], 0.f);
        Xs[lk + 0][lr] = t0; Xs[lk + 1][lr] = t1; Xs[lk + 2][lr] = t2; Xs[lk + 3][lr] = t3;
        if (tid < 32) {
            float4 wv = *(const float4*)(wrow + k0 + lk);
            Ws[lk + 0][c] = wv.x; Ws[lk + 1][c] = wv.y; Ws[lk + 2][c] = wv.z; Ws[lk + 3][c] = wv.w;
        }
        __syncthreads();
#pragma unroll
        for (int kk = 0; kk < 16; kk++) {
            float w = Ws[kk][tj];
            acc[0] += Xs[kk][tb] * w;
            acc[1] += Xs[kk][tb + 32] * w;
        }
        __syncthreads();
    }
    const int j = j0 + tj;
#pragma unroll
    for (int u = 0; u < 2; u++) {
        int b_ = tb + u * 32;
        float v = acc[u] + b2e[j] + res[(size_t)b_ * H + j];
        g_PREV[(size_t)b_ * H + j] = v;
        out[((size_t)b_ * S + t) * H + j] = v;
    }
}

// ---------------- gating: t=0 emo + 511 x (gate -> emo) in one persistent kernel ------
__global__ void k_gating_all(const float* __restrict__ Wf, const float* __restrict__ Wi,
                             const float* __restrict__ Wo, const float* __restrict__ Wc,
                             const float* __restrict__ bf, const float* __restrict__ bi,
                             const float* __restrict__ bo, const float* __restrict__ bc,
                             const float* __restrict__ spk, const float* __restrict__ pos,
                             const float* __restrict__ W1e, const float* __restrict__ b1e,
                             const float* __restrict__ gln, const float* __restrict__ bln,
                             const float* __restrict__ W2e, const float* __restrict__ b2e,
                             float* __restrict__ out) {
    __shared__ float Cs[16][65];
    __shared__ float WsG[16][33];
    __shared__ float Xs[16][65];
    __shared__ float Ws8[16][9];
    __shared__ float psum[8][64];
    __shared__ float psq[8][64];
    __shared__ float mu_s[64];
    __shared__ float rs_s[64];
    __shared__ float gl_s[H];
    __shared__ float bl_s[H];
    const int tid = threadIdx.x;
    for (int i = tid; i < H; i += 256) { gl_s[i] = gln[i]; bl_s[i] = bln[i]; }
    __syncthreads();

    // t = 0: prev0 = emo(mem[0])  (mem[0] has b*H row layout)
    emo1_phase(g_MEM, W1e, b1e, Xs, Ws8, psum, psq);
    grid_sync();
    emo2_phase(0, g_MEM, W2e, b2e, out, Xs, Ws8, mu_s, rs_s, gl_s, bl_s);
    grid_sync();

    for (int t = 1; t < S; t++) {
        gate_phase(t, Wf, Wi, Wo, Wc, bf, bi, bo, bc, spk, pos, Cs, WsG);
        grid_sync();
        emo1_phase(g_GATED, W1e, b1e, Xs, Ws8, psum, psq);
        grid_sync();
        emo2_phase(t, g_GATED, W2e, b2e, out, Xs, Ws8, mu_s, rs_s, gl_s, bl_s);
        grid_sync();
    }
}

// ---------------- host launch ----------------
extern "C" void kernel_launch(void* const* d_in, const int* in_sizes, int n_in,
                              void* d_out, int out_size) {
    (void)in_sizes; (void)n_in; (void)out_size;
    const float* utt   = (const float*)d_in[0];
    const float* spk   = (const float*)d_in[1];
    const float* pos   = (const float*)d_in[2];
    const float* Wih_f = (const float*)d_in[3];
    const float* Whh_f = (const float*)d_in[4];
    const float* bih_f = (const float*)d_in[5];
    const float* bhh_f = (const float*)d_in[6];
    const float* Wih_b = (const float*)d_in[7];
    const float* Whh_b = (const float*)d_in[8];
    const float* bih_b = (const float*)d_in[9];
    const float* bhh_b = (const float*)d_in[10];
    const float* Wf  = (const float*)d_in[11]; const float* bf_ = (const float*)d_in[12];
    const float* Wi  = (const float*)d_in[13]; const float* bi_ = (const float*)d_in[14];
    const float* Wo  = (const float*)d_in[15]; const float* bo_ = (const float*)d_in[16];
    const float* Wc  = (const float*)d_in[17]; const float* bc_ = (const float*)d_in[18];
    const float* W1e = (const float*)d_in[19]; const float* b1e = (const float*)d_in[20];
    const float* gln = (const float*)d_in[21]; const float* bln = (const float*)d_in[22];
    const float* W2e = (const float*)d_in[23]; const float* b2e = (const float*)d_in[24];
    float* out = (float*)d_out;

    // parallel input projections for both GRU directions
    dim3 gA(S, (2 * G3) / 64);
    k_xproj<<<gA, 256>>>(utt, Wih_f, bih_f, Wih_b, bih_b);

    // persistent GRU (all 512 steps, fwd + bwd fused)
    k_gru_all<<<NBLK, 256>>>(Whh_f, Whh_b, bhh_f, bhh_b);

    // persistent gating loop (all steps)
    k_gating_all<<<NBLK, 256>>>(Wf, Wi, Wo, Wc, bf_, bi_, bo_, bc_, spk, pos,
                                W1e, b1e, gln, bln, W2e, b2e, out);
}

// round 4
// speedup vs baseline: 1.0039x; 1.0039x over previous
#include <cuda_runtime.h>
#include <math.h>

#define S 512
#define B 64
#define D 1024
#define H 1024
#define H2 512
#define G3 1536
#define GIN 2080
#define LN_EPS 1e-5f
#define NBLK 128

// ---------------- scratch (device globals; no allocation) ----------------
__device__ float g_XPF[S * B * G3];        // forward  x-proj
__device__ float g_XPB[S * B * G3];        // backward x-proj
__device__ float g_MEM[S * B * H];         // GRU outputs [s][b][h]
__device__ float g_HST[2][2][B * H2];      // [dir][parity] hidden double-buffer
__device__ float g_PREV[B * H];            // recurrent prop state
__device__ float g_GATED[B * H];           // gate output per step
__device__ float g_H1[B * H];              // emo hidden (pre-LN)
__device__ float g_PS[NBLK * B];           // per-block partial row sums
__device__ float g_PS2[NBLK * B];          // per-block partial row sumsq

// ---------------- software grid barrier ----------------
__device__ volatile unsigned g_flag = 0;
__device__ unsigned g_count = 0;

__device__ __forceinline__ void grid_sync() {
    __syncthreads();
    if (threadIdx.x == 0) {
        unsigned old = g_flag;
        __threadfence();
        if (atomicAdd(&g_count, 1) == (unsigned)(gridDim.x - 1)) {
            g_count = 0;
            __threadfence();
            g_flag = old + 1;
        } else {
            while (g_flag == old) { __nanosleep(64); }
        }
        __threadfence();
    }
    __syncthreads();
}

__device__ __forceinline__ float sigf(float x) { return 1.0f / (1.0f + expf(-x)); }

// ---------------- xproj: [S*B,1024] @ [1024,3072] (Wih_f ++ Wih_b) ----------------
__global__ void k_xproj(const float* __restrict__ utt,
                        const float* __restrict__ Wih_f, const float* __restrict__ bih_f,
                        const float* __restrict__ Wih_b, const float* __restrict__ bih_b) {
    __shared__ float As[16][65];
    __shared__ float Bs[16][65];
    const int s  = blockIdx.x;
    const int n0 = blockIdx.y * 64;
    const bool isF = (n0 < G3);
    const float* __restrict__ W    = isF ? Wih_f : Wih_b;
    const float* __restrict__ bias = isF ? bih_f : bih_b;
    float* __restrict__ Out        = isF ? g_XPF : g_XPB;
    const int nw0 = isF ? n0 : (n0 - G3);

    const int tid = threadIdx.x;
    const int tx = tid & 15, ty = tid >> 4;
    const int lr = tid >> 2, lk = (tid & 3) * 4;

    float acc[4][4];
#pragma unroll
    for (int i = 0; i < 4; i++)
#pragma unroll
        for (int j = 0; j < 4; j++) acc[i][j] = 0.f;

    const float* arow = utt + (size_t)lr * (S * D) + (size_t)s * D;
    const float* brow = W + (size_t)(nw0 + lr) * D;

    for (int k0 = 0; k0 < D; k0 += 16) {
        float4 av = *(const float4*)(arow + k0 + lk);
        As[lk + 0][lr] = av.x; As[lk + 1][lr] = av.y; As[lk + 2][lr] = av.z; As[lk + 3][lr] = av.w;
        float4 bv = *(const float4*)(brow + k0 + lk);
        Bs[lk + 0][lr] = bv.x; Bs[lk + 1][lr] = bv.y; Bs[lk + 2][lr] = bv.z; Bs[lk + 3][lr] = bv.w;
        __syncthreads();
#pragma unroll
        for (int kk = 0; kk < 16; kk++) {
            float a[4], b[4];
#pragma unroll
            for (int u = 0; u < 4; u++) a[u] = As[kk][ty * 4 + u];
#pragma unroll
            for (int u = 0; u < 4; u++) b[u] = Bs[kk][tx * 4 + u];
#pragma unroll
            for (int i = 0; i < 4; i++)
#pragma unroll
                for (int j = 0; j < 4; j++) acc[i][j] += a[i] * b[j];
        }
        __syncthreads();
    }
#pragma unroll
    for (int i = 0; i < 4; i++) {
        int b_ = ty * 4 + i;
#pragma unroll
        for (int j = 0; j < 4; j++) {
            int n = nw0 + tx * 4 + j;
            Out[((size_t)s * B + b_) * G3 + n] = acc[i][j] + bias[n];
        }
    }
}

// ---------------- GRU: all 512 steps in one persistent kernel ----------------
__global__ void k_gru_all(const float* __restrict__ Whh_f, const float* __restrict__ Whh_b,
                          const float* __restrict__ bhh_f, const float* __restrict__ bhh_b) {
    __shared__ float Hs[16][65];
    __shared__ float Ws[16][25];
    const int bx  = blockIdx.x;
    const int dir = bx >> 6;
    const int j0  = (bx & 63) * 8;
    const float* __restrict__ Whh = dir ? Whh_b : Whh_f;
    const float* __restrict__ bhh = dir ? bhh_b : bhh_f;
    const int tid = threadIdx.x;
    const int tb = tid & 31, tj = tid >> 5;
    const int lr = tid >> 2, lk = (tid & 3) * 4;

    // zero hidden state double-buffers (re-done each launch/replay)
    for (int i = bx * 256 + tid; i < 2 * 2 * B * H2; i += NBLK * 256)
        (&g_HST[0][0][0])[i] = 0.0f;
    grid_sync();

    const int c  = tid >> 2;           // Ws loader (valid when tid < 96)
    const int jj = c / 3, gg = c % 3;
    const float* wrow = Whh + (size_t)(gg * H2 + j0 + jj) * H2;
    const int j = j0 + tj;
    const float bR = bhh[j], bZ = bhh[512 + j], bN = bhh[1024 + j];

    for (int t = 0; t < S; t++) {
        const float* __restrict__ hold = g_HST[dir][t & 1];
        float* __restrict__ hnew       = g_HST[dir][(t + 1) & 1];
        const float* __restrict__ XP = dir ? (g_XPB + (size_t)(S - 1 - t) * B * G3)
                                           : (g_XPF + (size_t)t * B * G3);
        float aR[2] = {0.f, 0.f}, aZ[2] = {0.f, 0.f}, aN[2] = {0.f, 0.f};

        for (int k0 = 0; k0 < H2; k0 += 16) {
            float4 hv = *(const float4*)(hold + lr * H2 + k0 + lk);
            Hs[lk + 0][lr] = hv.x; Hs[lk + 1][lr] = hv.y; Hs[lk + 2][lr] = hv.z; Hs[lk + 3][lr] = hv.w;
            if (tid < 96) {
                float4 wv = *(const float4*)(wrow + k0 + lk);
                Ws[lk + 0][c] = wv.x; Ws[lk + 1][c] = wv.y; Ws[lk + 2][c] = wv.z; Ws[lk + 3][c] = wv.w;
            }
            __syncthreads();
#pragma unroll
            for (int kk = 0; kk < 16; kk++) {
                float h0 = Hs[kk][tb], h1 = Hs[kk][tb + 32];
                float wr = Ws[kk][tj * 3 + 0], wz = Ws[kk][tj * 3 + 1], wn = Ws[kk][tj * 3 + 2];
                aR[0] += h0 * wr; aZ[0] += h0 * wz; aN[0] += h0 * wn;
                aR[1] += h1 * wr; aZ[1] += h1 * wz; aN[1] += h1 * wn;
            }
            __syncthreads();
        }
        const int s_out = dir ? (S - 1 - t) : t;
#pragma unroll
        for (int u = 0; u < 2; u++) {
            int b_ = tb + u * 32;
            const float* xrow = XP + (size_t)b_ * G3;
            float xr = xrow[j], xz = xrow[512 + j], xn = xrow[1024 + j];
            float r  = sigf(xr + aR[u] + bR);
            float z  = sigf(xz + aZ[u] + bZ);
            float nn = tanhf(xn + r * (aN[u] + bN));
            float hp = hold[b_ * H2 + j];
            float h  = (1.f - z) * nn + z * hp;
            hnew[b_ * H2 + j] = h;
            g_MEM[((size_t)s_out * B + b_) * H + dir * H2 + j] = h;
        }
        grid_sync();
    }
}

// ---------------- gating loop phases ----------------
__device__ void gate_phase(int t,
                           const float* __restrict__ Wf, const float* __restrict__ Wi,
                           const float* __restrict__ Wo, const float* __restrict__ Wc,
                           const float* __restrict__ bf, const float* __restrict__ bi,
                           const float* __restrict__ bo, const float* __restrict__ bc,
                           const float* __restrict__ spk, const float* __restrict__ pos,
                           float Cs[16][65], float Ws[16][33]) {
    const int j0  = blockIdx.x * 8;
    const int tid = threadIdx.x;
    const int tb = tid & 31, tj = tid >> 5;
    const int lr = tid >> 2, lk = (tid & 3) * 4;
    float acc[2][4];
#pragma unroll
    for (int u = 0; u < 2; u++)
#pragma unroll
        for (int g = 0; g < 4; g++) acc[u][g] = 0.f;

    const float* __restrict__ memrow = g_MEM + (size_t)t * B * H;

    const int c  = tid >> 2;           // Ws loader (valid when tid < 128)
    const int jj = c >> 2, gg = c & 3;
    const float* wsel = (gg == 0) ? Wf : ((gg == 1) ? Wi : ((gg == 2) ? Wo : Wc));
    const float* wrow = wsel + (size_t)(j0 + jj) * GIN;

    for (int k0 = 0; k0 < GIN; k0 += 16) {
        const int k = k0 + lk;
        float4 v;
        if (k < 1024)      v = *(const float4*)(memrow + (size_t)lr * H + k);
        else if (k < 2048) v = *(const float4*)(g_PREV + (size_t)lr * H + (k - 1024));
        else if (k < 2064) v = *(const float4*)(spk + ((size_t)lr * S + t) * 16 + (k - 2048));
        else               v = *(const float4*)(pos + ((size_t)lr * S + t) * 16 + (k - 2064));
        Cs[lk + 0][lr] = v.x; Cs[lk + 1][lr] = v.y; Cs[lk + 2][lr] = v.z; Cs[lk + 3][lr] = v.w;
        if (tid < 128) {
            float4 wv = *(const float4*)(wrow + k0 + lk);
            Ws[lk + 0][c] = wv.x; Ws[lk + 1][c] = wv.y; Ws[lk + 2][c] = wv.z; Ws[lk + 3][c] = wv.w;
        }
        __syncthreads();
#pragma unroll
        for (int kk = 0; kk < 16; kk++) {
            float a0 = Cs[kk][tb], a1 = Cs[kk][tb + 32];
#pragma unroll
            for (int g = 0; g < 4; g++) {
                float w = Ws[kk][tj * 4 + g];
                acc[0][g] += a0 * w;
                acc[1][g] += a1 * w;
            }
        }
        __syncthreads();
    }
    const int j = j0 + tj;
    const float bfv = bf[j], biv = bi[j], bov = bo[j], bcv = bc[j];
#pragma unroll
    for (int u = 0; u < 2; u++) {
        int b_ = tb + u * 32;
        float f  = sigf(acc[u][0] + bfv);
        float ig = sigf(acc[u][1] + biv);
        float o  = sigf(acc[u][2] + bov);
        float cg = tanhf(acc[u][3] + bcv);
        float pv = g_PREV[b_ * H + j];
        float ns = f * pv + ig * cg;
        g_GATED[b_ * H + j] = o * tanhf(ns);
    }
}

__device__ void emo1_phase(const float* __restrict__ x,
                           const float* __restrict__ W1e, const float* __restrict__ b1e,
                           float Xs[16][65], float Ws[16][9],
                           float psum[8][64], float psq[8][64]) {
    const int j0  = blockIdx.x * 8;
    const int tid = threadIdx.x;
    const int tb = tid & 31, tj = tid >> 5;
    const int lr = tid >> 2, lk = (tid & 3) * 4;
    float acc[2] = {0.f, 0.f};
    const int c = tid >> 2;            // Ws loader (valid tid < 32)
    const float* wrow = W1e + (size_t)(j0 + c) * H;

    for (int k0 = 0; k0 < H; k0 += 16) {
        float4 xv = *(const float4*)(x + (size_t)lr * H + k0 + lk);
        Xs[lk + 0][lr] = xv.x; Xs[lk + 1][lr] = xv.y; Xs[lk + 2][lr] = xv.z; Xs[lk + 3][lr] = xv.w;
        if (tid < 32) {
            float4 wv = *(const float4*)(wrow + k0 + lk);
            Ws[lk + 0][c] = wv.x; Ws[lk + 1][c] = wv.y; Ws[lk + 2][c] = wv.z; Ws[lk + 3][c] = wv.w;
        }
        __syncthreads();
#pragma unroll
        for (int kk = 0; kk < 16; kk++) {
            float w = Ws[kk][tj];
            acc[0] += Xs[kk][tb] * w;
            acc[1] += Xs[kk][tb + 32] * w;
        }
        __syncthreads();
    }
    const int j = j0 + tj;
    float v0 = acc[0] + b1e[j];
    float v1 = acc[1] + b1e[j];
    g_H1[(size_t)tb * H + j] = v0;
    g_H1[(size_t)(tb + 32) * H + j] = v1;
    psum[tj][tb] = v0;       psum[tj][tb + 32] = v1;
    psq[tj][tb]  = v0 * v0;  psq[tj][tb + 32]  = v1 * v1;
    __syncthreads();
    if (tid < 64) {
        float s = 0.f, s2 = 0.f;
#pragma unroll
        for (int q = 0; q < 8; q++) { s += psum[q][tid]; s2 += psq[q][tid]; }
        g_PS[blockIdx.x * B + tid]  = s;
        g_PS2[blockIdx.x * B + tid] = s2;
    }
}

__device__ void emo2_phase(int t, const float* __restrict__ res,
                           const float* __restrict__ W2e, const float* __restrict__ b2e,
                           float* __restrict__ out,
                           float Xs[16][65], float Ws[16][9],
                           float mu_s[64], float rs_s[64],
                           const float* gl_s, const float* bl_s) {
    const int j0  = blockIdx.x * 8;
    const int tid = threadIdx.x;
    const int tb = tid & 31, tj = tid >> 5;
    const int lr = tid >> 2, lk = (tid & 3) * 4;

    if (tid < 64) {
        float s = 0.f, s2 = 0.f;
        for (int q = 0; q < NBLK; q++) { s += g_PS[q * B + tid]; s2 += g_PS2[q * B + tid]; }
        float mu  = s * (1.0f / H);
        float var = s2 * (1.0f / H) - mu * mu;
        mu_s[tid] = mu;
        rs_s[tid] = rsqrtf(var + LN_EPS);
    }
    __syncthreads();

    float acc[2] = {0.f, 0.f};
    const int c = tid >> 2;
    const float* wrow = W2e + (size_t)(j0 + c) * H;
    const float mu_l = mu_s[lr], rs_l = rs_s[lr];

    for (int k0 = 0; k0 < H; k0 += 16) {
        float4 xv = *(const float4*)(g_H1 + (size_t)lr * H + k0 + lk);
        float t0 = fmaxf((xv.x - mu_l) * rs_l * gl_s[k0 + lk + 0] + bl_s[k0 + lk + 0], 0.f);
        float t1 = fmaxf((xv.y - mu_l) * rs_l * gl_s[k0 + lk + 1] + bl_s[k0 + lk + 1], 0.f);
        float t2 = fmaxf((xv.z - mu_l) * rs_l * gl_s[k0 + lk + 2] + bl_s[k0 + lk + 2], 0.f);
        float t3 = fmaxf((xv.w - mu_l) * rs_l * gl_s[k0 + lk + 3] + bl_s[k0 + lk + 3], 0.f);
        Xs[lk + 0][lr] = t0; Xs[lk + 1][lr] = t1; Xs[lk + 2][lr] = t2; Xs[lk + 3][lr] = t3;
        if (tid < 32) {
            float4 wv = *(const float4*)(wrow + k0 + lk);
            Ws[lk + 0][c] = wv.x; Ws[lk + 1][c] = wv.y; Ws[lk + 2][c] = wv.z; Ws[lk + 3][c] = wv.w;
        }
        __syncthreads();
#pragma unroll
        for (int kk = 0; kk < 16; kk++) {
            float w = Ws[kk][tj];
            acc[0] += Xs[kk][tb] * w;
            acc[1] += Xs[kk][tb + 32] * w;
        }
        __syncthreads();
    }
    const int j = j0 + tj;
#pragma unroll
    for (int u = 0; u < 2; u++) {
        int b_ = tb + u * 32;
        float v = acc[u] + b2e[j] + res[(size_t)b_ * H + j];
        g_PREV[(size_t)b_ * H + j] = v;
        out[((size_t)b_ * S + t) * H + j] = v;
    }
}

// ---------------- gating: t=0 emo + 511 x (gate -> emo) in one persistent kernel ------
__global__ void k_gating_all(const float* __restrict__ Wf, const float* __restrict__ Wi,
                             const float* __restrict__ Wo, const float* __restrict__ Wc,
                             const float* __restrict__ bf, const float* __restrict__ bi,
                             const float* __restrict__ bo, const float* __restrict__ bc,
                             const float* __restrict__ spk, const float* __restrict__ pos,
                             const float* __restrict__ W1e, const float* __restrict__ b1e,
                             const float* __restrict__ gln, const float* __restrict__ bln,
                             const float* __restrict__ W2e, const float* __restrict__ b2e,
                             float* __restrict__ out) {
    __shared__ float Cs[16][65];
    __shared__ float WsG[16][33];
    __shared__ float Xs[16][65];
    __shared__ float Ws8[16][9];
    __shared__ float psum[8][64];
    __shared__ float psq[8][64];
    __shared__ float mu_s[64];
    __shared__ float rs_s[64];
    __shared__ float gl_s[H];
    __shared__ float bl_s[H];
    const int tid = threadIdx.x;
    for (int i = tid; i < H; i += 256) { gl_s[i] = gln[i]; bl_s[i] = bln[i]; }
    __syncthreads();

    // t = 0: prev0 = emo(mem[0])  (mem[0] has b*H row layout)
    emo1_phase(g_MEM, W1e, b1e, Xs, Ws8, psum, psq);
    grid_sync();
    emo2_phase(0, g_MEM, W2e, b2e, out, Xs, Ws8, mu_s, rs_s, gl_s, bl_s);
    grid_sync();

    for (int t = 1; t < S; t++) {
        gate_phase(t, Wf, Wi, Wo, Wc, bf, bi, bo, bc, spk, pos, Cs, WsG);
        grid_sync();
        emo1_phase(g_GATED, W1e, b1e, Xs, Ws8, psum, psq);
        grid_sync();
        emo2_phase(t, g_GATED, W2e, b2e, out, Xs, Ws8, mu_s, rs_s, gl_s, bl_s);
        grid_sync();
    }
}

// ---------------- host launch ----------------
extern "C" void kernel_launch(void* const* d_in, const int* in_sizes, int n_in,
                              void* d_out, int out_size) {
    (void)in_sizes; (void)n_in; (void)out_size;
    const float* utt   = (const float*)d_in[0];
    const float* spk   = (const float*)d_in[1];
    const float* pos   = (const float*)d_in[2];
    const float* Wih_f = (const float*)d_in[3];
    const float* Whh_f = (const float*)d_in[4];
    const float* bih_f = (const float*)d_in[5];
    const float* bhh_f = (const float*)d_in[6];
    const float* Wih_b = (const float*)d_in[7];
    const float* Whh_b = (const float*)d_in[8];
    const float* bih_b = (const float*)d_in[9];
    const float* bhh_b = (const float*)d_in[10];
    const float* Wf  = (const float*)d_in[11]; const float* bf_ = (const float*)d_in[12];
    const float* Wi  = (const float*)d_in[13]; const float* bi_ = (const float*)d_in[14];
    const float* Wo  = (const float*)d_in[15]; const float* bo_ = (const float*)d_in[16];
    const float* Wc  = (const float*)d_in[17]; const float* bc_ = (const float*)d_in[18];
    const float* W1e = (const float*)d_in[19]; const float* b1e = (const float*)d_in[20];
    const float* gln = (const float*)d_in[21]; const float* bln = (const float*)d_in[22];
    const float* W2e = (const float*)d_in[23]; const float* b2e = (const float*)d_in[24];
    float* out = (float*)d_out;

    // parallel input projections for both GRU directions
    dim3 gA(S, (2 * G3) / 64);
    k_xproj<<<gA, 256>>>(utt, Wih_f, bih_f, Wih_b, bih_b);

    // persistent GRU (all 512 steps, fwd + bwd fused)
    k_gru_all<<<NBLK, 256>>>(Whh_f, Whh_b, bhh_f, bhh_b);

    // persistent gating loop (all steps)
    k_gating_all<<<NBLK, 256>>>(Wf, Wi, Wo, Wc, bf_, bi_, bo_, bc_, spk, pos,
                                W1e, b1e, gln, bln, W2e, b2e, out);
}